// round 1
// baseline (speedup 1.0000x reference)
#include <cuda_runtime.h>
#include <cuda_bf16.h>

// Problem constants (fixed by the reference):
//   T=20 timesteps, G=1024 groups, P=64 peds/group, THR=0.25
//   out[g*P*P*T + (i*P+j)*T + t] = (i==j) ? 0 : relu(THR - dist(g,t,i,j))
// trajectory_relative and seq_start_end are unused (uniform contiguous groups).

#define TT 20
#define GG 1024
#define PP 64
#define THRC 0.25f
#define CHUNKS 10
#define NTHREADS 256

// per group: P*P*T = 81920 floats = 20480 float4
// per chunk: 2048 float4 -> 8 per thread at 256 threads

__global__ __launch_bounds__(NTHREADS)
void traj_cost_kernel(const float2* __restrict__ traj, float4* __restrict__ out) {
    const int g = blockIdx.y;
    const int chunk = blockIdx.x;

    // Padded tile: [t][p], +1 float2 row padding to avoid stride-64 bank conflicts
    __shared__ float2 xs[TT][PP + 1];

    // Load this group's slab: trajectory[t][g*P + p] as float2, coalesced per-t rows
    const float2* gsrc = traj + (size_t)g * PP;
    #pragma unroll
    for (int idx = threadIdx.x; idx < TT * PP; idx += NTHREADS) {
        int t = idx >> 6;          // /64
        int p = idx & (PP - 1);    // %64
        xs[t][p] = gsrc[(size_t)t * (GG * PP) + p];
    }
    __syncthreads();

    const int Q4_PER_GROUP = PP * PP * TT / 4;       // 20480
    const int Q4_PER_CHUNK = Q4_PER_GROUP / CHUNKS;  // 2048

    float4* gout = out + (size_t)g * Q4_PER_GROUP;
    const int base = chunk * Q4_PER_CHUNK;

    #pragma unroll 2
    for (int q4 = base + threadIdx.x; q4 < base + Q4_PER_CHUNK; q4 += NTHREADS) {
        // q4 = pair*5 + m, pair = i*64 + j, t0 = 4*m  (T/4 == 5)
        int pair = q4 / 5;
        int m = q4 - pair * 5;
        int t0 = m << 2;
        int i = pair >> 6;
        int j = pair & (PP - 1);

        float v[4];
        if (i == j) {
            v[0] = v[1] = v[2] = v[3] = 0.0f;
        } else {
            #pragma unroll
            for (int k = 0; k < 4; k++) {
                float2 a = xs[t0 + k][i];
                float2 b = xs[t0 + k][j];
                float dx = a.x - b.x;
                float dy = a.y - b.y;
                float d = sqrtf(fmaf(dx, dx, dy * dy));
                v[k] = fmaxf(0.0f, THRC - d);
            }
        }
        gout[q4] = *reinterpret_cast<const float4*>(v);
    }
}

extern "C" void kernel_launch(void* const* d_in, const int* in_sizes, int n_in,
                              void* d_out, int out_size) {
    const float2* traj = (const float2*)d_in[0];  // trajectory (T, G*P, 2)
    float4* out = (float4*)d_out;                  // (G*P*P*T) fp32

    dim3 grid(CHUNKS, GG);
    traj_cost_kernel<<<grid, NTHREADS>>>(traj, out);
}

// round 2
// speedup vs baseline: 1.0224x; 1.0224x over previous
#include <cuda_runtime.h>
#include <cuda_bf16.h>

// Problem constants (fixed by the reference):
//   T=20 timesteps, G=1024 groups, P=64 peds/group, THR=0.25
//   out[g*P*P*T + (i*P+j)*T + t] = (i==j) ? 0 : relu(THR - dist(g,t,i,j))
// trajectory_relative and seq_start_end are unused (uniform contiguous groups).

#define TT 20
#define GG 1024
#define PP 64
#define THRC 0.25f
#define CHUNKS 10
#define NTHREADS 256

// smem tile layout: pedestrian-major, row = 22 float2 (176 B, multiple of 16 B
// so &xs[p][t0] with t0 % 2 == 0 is 16B-aligned for LDS.128).
#define TPAD 22

__global__ __launch_bounds__(NTHREADS)
void traj_cost_kernel(const float2* __restrict__ traj, float4* __restrict__ out) {
    const int g = blockIdx.y;
    const int chunk = blockIdx.x;

    __shared__ float2 xs[PP][TPAD];   // [pedestrian][timestep], padded row

    // Load group slab, transposing t-major global -> p-major smem.
    // Global reads stay coalesced (per-t rows of 64 consecutive float2).
    const float2* gsrc = traj + (size_t)g * PP;
    #pragma unroll
    for (int idx = threadIdx.x; idx < TT * PP; idx += NTHREADS) {
        int t = idx >> 6;          // /64
        int p = idx & (PP - 1);    // %64
        xs[p][t] = gsrc[(size_t)t * (GG * PP) + p];
    }
    __syncthreads();

    const int Q4_PER_GROUP = PP * PP * TT / 4;       // 20480
    const int Q4_PER_CHUNK = Q4_PER_GROUP / CHUNKS;  // 2048

    float4* gout = out + (size_t)g * Q4_PER_GROUP;
    const int base = chunk * Q4_PER_CHUNK;

    #pragma unroll 2
    for (int q4 = base + threadIdx.x; q4 < base + Q4_PER_CHUNK; q4 += NTHREADS) {
        // q4 = pair*5 + m, pair = i*64 + j, t0 = 4*m  (T/4 == 5)
        int pair = q4 / 5;
        int m = q4 - pair * 5;
        int t0 = m << 2;
        int i = pair >> 6;
        int j = pair & (PP - 1);

        float4 v;
        if (i == j) {
            v = make_float4(0.0f, 0.0f, 0.0f, 0.0f);
        } else {
            // 4 consecutive timesteps are contiguous in the transposed tile:
            // two LDS.128 per operand.
            const float4* ap = reinterpret_cast<const float4*>(&xs[i][t0]);
            const float4* bp = reinterpret_cast<const float4*>(&xs[j][t0]);
            float4 a01 = ap[0];   // (x_t0, y_t0, x_t0+1, y_t0+1)
            float4 a23 = ap[1];   // (x_t0+2, y_t0+2, x_t0+3, y_t0+3)
            float4 b01 = bp[0];
            float4 b23 = bp[1];

            float dx0 = a01.x - b01.x, dy0 = a01.y - b01.y;
            float dx1 = a01.z - b01.z, dy1 = a01.w - b01.w;
            float dx2 = a23.x - b23.x, dy2 = a23.y - b23.y;
            float dx3 = a23.z - b23.z, dy3 = a23.w - b23.w;

            v.x = fmaxf(0.0f, THRC - sqrtf(fmaf(dx0, dx0, dy0 * dy0)));
            v.y = fmaxf(0.0f, THRC - sqrtf(fmaf(dx1, dx1, dy1 * dy1)));
            v.z = fmaxf(0.0f, THRC - sqrtf(fmaf(dx2, dx2, dy2 * dy2)));
            v.w = fmaxf(0.0f, THRC - sqrtf(fmaf(dx3, dx3, dy3 * dy3)));
        }
        gout[q4] = v;
    }
}

extern "C" void kernel_launch(void* const* d_in, const int* in_sizes, int n_in,
                              void* d_out, int out_size) {
    const float2* traj = (const float2*)d_in[0];  // trajectory (T, G*P, 2)
    float4* out = (float4*)d_out;                  // (G*P*P*T) fp32

    dim3 grid(CHUNKS, GG);
    traj_cost_kernel<<<grid, NTHREADS>>>(traj, out);
}

// round 3
// speedup vs baseline: 1.5193x; 1.4860x over previous
#include <cuda_runtime.h>
#include <cuda_bf16.h>

// Problem constants (fixed by the reference):
//   T=20 timesteps, G=1024 groups, P=64 peds/group, THR=0.25
//   out[g*P*P*T + (i*P+j)*T + t] = (i==j) ? 0 : relu(THR - dist(g,t,i,j))
// trajectory_relative and seq_start_end are unused (uniform contiguous groups).

#define TT 20
#define GG 1024
#define PP 64
#define THRC 0.25f
#define NTHREADS 320          // = P * (T/4) / ISPLIT_j ... here: 64 j * 5 m
#define ISPLIT 2              // blocks per group along i
#define IPB (PP / ISPLIT)     // 32 i-iterations per block

// smem tile: pedestrian-major, row padded to 22 float2 = 176 B (16B multiple)
#define TPAD 22

__global__ __launch_bounds__(NTHREADS)
void traj_cost_kernel(const float2* __restrict__ traj, float* __restrict__ out) {
    const int g = blockIdx.y;
    const int i0 = blockIdx.x * IPB;

    __shared__ float2 xs[PP][TPAD];   // [pedestrian][timestep]

    // Load group slab, transposing t-major global -> p-major smem.
    // Global reads coalesced (per-t rows of 64 consecutive float2).
    const float2* gsrc = traj + (size_t)g * PP;
    #pragma unroll
    for (int idx = threadIdx.x; idx < TT * PP; idx += NTHREADS) {
        int t = idx >> 6;          // /64
        int p = idx & (PP - 1);    // %64
        xs[p][t] = gsrc[(size_t)t * (GG * PP) + p];
    }
    __syncthreads();

    // Thread identity: tid = j*5 + m  (j = other pedestrian, m = t-chunk)
    const int j  = threadIdx.x / 5;
    const int m  = threadIdx.x - j * 5;
    const int t0 = m << 2;

    // Operand b_j: this thread's 4 timesteps, kept in registers for all i.
    const float4* bp = reinterpret_cast<const float4*>(&xs[j][t0]);
    const float4 b01 = bp[0];   // (x_t0, y_t0, x_t0+1, y_t0+1)
    const float4 b23 = bp[1];

    // Store base: out[g*P*P*T + i*P*T + j*T + t0]; per warp this is 512 B
    // contiguous (tid*16 B), perfectly coalesced STG.128.
    float* gout = out + (size_t)g * (PP * PP * TT) + (size_t)j * TT + t0;

    #pragma unroll 4
    for (int ii = 0; ii < IPB; ii++) {
        const int i = i0 + ii;

        const float4* ap = reinterpret_cast<const float4*>(&xs[i][t0]);
        float4 a01 = ap[0];
        float4 a23 = ap[1];

        float4 v;
        if (i == j) {
            v = make_float4(0.0f, 0.0f, 0.0f, 0.0f);
        } else {
            float dx0 = a01.x - b01.x, dy0 = a01.y - b01.y;
            float dx1 = a01.z - b01.z, dy1 = a01.w - b01.w;
            float dx2 = a23.x - b23.x, dy2 = a23.y - b23.y;
            float dx3 = a23.z - b23.z, dy3 = a23.w - b23.w;

            v.x = fmaxf(0.0f, THRC - sqrtf(fmaf(dx0, dx0, dy0 * dy0)));
            v.y = fmaxf(0.0f, THRC - sqrtf(fmaf(dx1, dx1, dy1 * dy1)));
            v.z = fmaxf(0.0f, THRC - sqrtf(fmaf(dx2, dx2, dy2 * dy2)));
            v.w = fmaxf(0.0f, THRC - sqrtf(fmaf(dx3, dx3, dy3 * dy3)));
        }
        *reinterpret_cast<float4*>(gout + (size_t)i * (PP * TT)) = v;
    }
}

extern "C" void kernel_launch(void* const* d_in, const int* in_sizes, int n_in,
                              void* d_out, int out_size) {
    const float2* traj = (const float2*)d_in[0];  // trajectory (T, G*P, 2)
    float* out = (float*)d_out;                    // (G*P*P*T) fp32

    dim3 grid(ISPLIT, GG);
    traj_cost_kernel<<<grid, NTHREADS>>>(traj, out);
}

// round 4
// speedup vs baseline: 1.6759x; 1.1031x over previous
#include <cuda_runtime.h>
#include <cuda_bf16.h>
#include <cstdint>

// Problem constants (fixed by the reference):
//   T=20 timesteps, G=1024 groups, P=64 peds/group, THR=0.25
//   out[g*P*P*T + (i*P+j)*T + t] = (i==j) ? 0 : relu(THR - dist(g,t,i,j))
// trajectory_relative and seq_start_end are unused (uniform contiguous groups).

#define TT 20
#define GG 1024
#define PP 64
#define THRC 0.25f
#define NTHREADS 320          // 64 j * 5 t-chunks
#define ISPLIT 2              // blocks per group along i
#define IPB (PP / ISPLIT)     // 32 i-iterations per block

// smem tile: pedestrian-major, row padded to 22 float2 = 176 B (16B multiple)
#define TPAD 22

__device__ __forceinline__ uint64_t f32x2_add(uint64_t a, uint64_t b) {
    uint64_t r;
    asm("add.rn.f32x2 %0, %1, %2;" : "=l"(r) : "l"(a), "l"(b));
    return r;
}
__device__ __forceinline__ uint64_t f32x2_mul(uint64_t a, uint64_t b) {
    uint64_t r;
    asm("mul.rn.f32x2 %0, %1, %2;" : "=l"(r) : "l"(a), "l"(b));
    return r;
}
__device__ __forceinline__ float2 unpack_f32x2(uint64_t v) {
    float lo, hi;
    asm("mov.b64 {%0, %1}, %2;" : "=f"(lo), "=f"(hi) : "l"(v));
    return make_float2(lo, hi);
}
__device__ __forceinline__ uint64_t pack_f32x2(float lo, float hi) {
    uint64_t r;
    asm("mov.b64 %0, {%1, %2};" : "=l"(r) : "f"(lo), "f"(hi));
    return r;
}
__device__ __forceinline__ float sqrt_approx(float x) {
    float r;
    asm("sqrt.approx.f32 %0, %1;" : "=f"(r) : "f"(x));
    return r;
}

__global__ __launch_bounds__(NTHREADS)
void traj_cost_kernel(const float2* __restrict__ traj, float* __restrict__ out) {
    const int g = blockIdx.y;
    const int i0 = blockIdx.x * IPB;

    __shared__ float2 xs[PP][TPAD];   // [pedestrian][timestep]

    // Load group slab, transposing t-major global -> p-major smem.
    const float2* gsrc = traj + (size_t)g * PP;
    #pragma unroll
    for (int idx = threadIdx.x; idx < TT * PP; idx += NTHREADS) {
        int t = idx >> 6;          // /64
        int p = idx & (PP - 1);    // %64
        xs[p][t] = gsrc[(size_t)t * (GG * PP) + p];
    }
    __syncthreads();

    // Thread identity: tid = j*5 + m  (j = other pedestrian, m = t-chunk)
    const int j  = threadIdx.x / 5;
    const int m  = threadIdx.x - j * 5;
    const int t0 = m << 2;

    // Operand b_j: this thread's 4 timesteps, negated and packed as f32x2,
    // kept in registers for all i.
    const float4* bp = reinterpret_cast<const float4*>(&xs[j][t0]);
    const float4 b01 = bp[0];   // (x_t0, y_t0, x_t0+1, y_t0+1)
    const float4 b23 = bp[1];
    const uint64_t nb0 = pack_f32x2(-b01.x, -b01.y);
    const uint64_t nb1 = pack_f32x2(-b01.z, -b01.w);
    const uint64_t nb2 = pack_f32x2(-b23.x, -b23.y);
    const uint64_t nb3 = pack_f32x2(-b23.z, -b23.w);

    // Store base: out[g*P*P*T + i*P*T + j*T + t0]; per warp this is 512 B
    // contiguous (tid*16 B), perfectly coalesced STG.128.
    float* gout = out + (size_t)g * (PP * PP * TT) + (size_t)j * TT + t0;

    #pragma unroll 4
    for (int ii = 0; ii < IPB; ii++) {
        const int i = i0 + ii;

        const ulonglong2* ap = reinterpret_cast<const ulonglong2*>(&xs[i][t0]);
        ulonglong2 a01 = ap[0];   // .x = (x_t0,y_t0)  .y = (x_t0+1,y_t0+1)
        ulonglong2 a23 = ap[1];

        float4 v;
        if (i == j) {
            v = make_float4(0.0f, 0.0f, 0.0f, 0.0f);
        } else {
            uint64_t d0 = f32x2_add(a01.x, nb0);
            uint64_t d1 = f32x2_add(a01.y, nb1);
            uint64_t d2 = f32x2_add(a23.x, nb2);
            uint64_t d3 = f32x2_add(a23.y, nb3);

            uint64_t s0 = f32x2_mul(d0, d0);
            uint64_t s1 = f32x2_mul(d1, d1);
            uint64_t s2 = f32x2_mul(d2, d2);
            uint64_t s3 = f32x2_mul(d3, d3);

            float2 q0 = unpack_f32x2(s0);
            float2 q1 = unpack_f32x2(s1);
            float2 q2 = unpack_f32x2(s2);
            float2 q3 = unpack_f32x2(s3);

            v.x = fmaxf(0.0f, THRC - sqrt_approx(q0.x + q0.y));
            v.y = fmaxf(0.0f, THRC - sqrt_approx(q1.x + q1.y));
            v.z = fmaxf(0.0f, THRC - sqrt_approx(q2.x + q2.y));
            v.w = fmaxf(0.0f, THRC - sqrt_approx(q3.x + q3.y));
        }
        // Streaming store: output is write-once, keep it out of L2's way.
        __stcs(reinterpret_cast<float4*>(gout + (size_t)i * (PP * TT)), v);
    }
}

extern "C" void kernel_launch(void* const* d_in, const int* in_sizes, int n_in,
                              void* d_out, int out_size) {
    const float2* traj = (const float2*)d_in[0];  // trajectory (T, G*P, 2)
    float* out = (float*)d_out;                    // (G*P*P*T) fp32

    dim3 grid(ISPLIT, GG);
    traj_cost_kernel<<<grid, NTHREADS>>>(traj, out);
}